// round 1
// baseline (speedup 1.0000x reference)
#include <cuda_runtime.h>
#include <cuda_bf16.h>

#define NN 50000
#define NE 800000
#define FD 128
#define NBITS 64
#define NCLS 100
#define HDIM 300

// ---------------- scratch (device globals: allocation-free) ----------------
__device__ int   g_cursor[NN];
__device__ int   g_rowptr[NN + 1];
__device__ int   g_partials[128];
__device__ int   g_col[NE];
__device__ float g_mean[NN * FD];
__device__ float g_h1[NN * FD];
__device__ float g_h2[NN * FD];
__device__ float g_prebn[NN * NBITS];

// ---------------- CSR build: counting sort by dst ----------------
__global__ void zero_k() {
    int i = blockIdx.x * blockDim.x + threadIdx.x;
    if (i < NN) g_cursor[i] = 0;
}

__global__ void hist_k(const int* __restrict__ dst) {
    for (int e = blockIdx.x * blockDim.x + threadIdx.x; e < NE; e += gridDim.x * blockDim.x)
        atomicAdd(&g_cursor[dst[e]], 1);
}

// block-wise exclusive scan of g_cursor -> g_rowptr, block totals -> g_partials
__global__ void scan1_k() {
    int i = blockIdx.x * 512 + threadIdx.x;
    int v = (i < NN) ? g_cursor[i] : 0;
    int lane = threadIdx.x & 31, w = threadIdx.x >> 5;
    int x = v;
    #pragma unroll
    for (int o = 1; o < 32; o <<= 1) {
        int y = __shfl_up_sync(0xffffffffu, x, o);
        if (lane >= o) x += y;
    }
    __shared__ int wsum[16];
    if (lane == 31) wsum[w] = x;
    __syncthreads();
    if (w == 0) {
        int s = (lane < 16) ? wsum[lane] : 0;
        #pragma unroll
        for (int o = 1; o < 16; o <<= 1) {
            int y = __shfl_up_sync(0xffffffffu, s, o);
            if (lane >= o) s += y;
        }
        if (lane < 16) wsum[lane] = s;
    }
    __syncthreads();
    int incl = x + (w > 0 ? wsum[w - 1] : 0);
    int excl = incl - v;
    if (i < NN) g_rowptr[i] = excl;
    if (threadIdx.x == 511) g_partials[blockIdx.x] = incl;
}

__global__ void scan2_k(int nb) {
    if (threadIdx.x == 0) {
        int run = 0;
        for (int b = 0; b < nb; b++) { int t = g_partials[b]; g_partials[b] = run; run += t; }
    }
}

__global__ void scan3_k() {
    int i = blockIdx.x * 512 + threadIdx.x;
    if (i < NN) {
        int v = g_rowptr[i] + g_partials[blockIdx.x];
        g_rowptr[i] = v;
        g_cursor[i] = v;
    }
    if (i == 0) g_rowptr[NN] = NE;
}

__global__ void scatter_k(const int* __restrict__ src, const int* __restrict__ dst) {
    for (int e = blockIdx.x * blockDim.x + threadIdx.x; e < NE; e += gridDim.x * blockDim.x) {
        int pos = atomicAdd(&g_cursor[dst[e]], 1);
        g_col[pos] = src[e];
    }
}

// ---------------- mean aggregation: one warp per node ----------------
__global__ void agg_k(const float* __restrict__ x, float* __restrict__ out) {
    int warp = blockIdx.x * (blockDim.x >> 5) + (threadIdx.x >> 5);
    int lane = threadIdx.x & 31;
    if (warp >= NN) return;
    int beg = g_rowptr[warp], end = g_rowptr[warp + 1];
    float4 acc = make_float4(0.f, 0.f, 0.f, 0.f);
    for (int e = beg; e < end; ++e) {
        int s = __ldg(&g_col[e]);
        float4 v = *(const float4*)(x + (size_t)s * FD + lane * 4);
        acc.x += v.x; acc.y += v.y; acc.z += v.z; acc.w += v.w;
    }
    float sc = 1.f / (float)max(end - beg, 1);
    float4 r = make_float4(acc.x * sc, acc.y * sc, acc.z * sc, acc.w * sc);
    *(float4*)(out + (size_t)warp * FD + lane * 4) = r;
}

// ---------------- generic fused SIMT GEMM ----------------
// C[M,N] = epilogue( A1[M,K]@W1[K,N] (+ A2@W2) + bias )
// MODE 0: none, 1: relu, 2: BN(eval)+tanh (writes pre-BN to preout, tanh to out)
template <int MODE, bool DUAL>
__global__ void __launch_bounds__(128, 4)
gemm_k(const float* __restrict__ A1, const float* __restrict__ W1,
       const float* __restrict__ A2, const float* __restrict__ W2,
       const float* __restrict__ bias, float* __restrict__ out,
       int M, int N, int K,
       const float* __restrict__ gamma, const float* __restrict__ beta,
       const float* __restrict__ rmean, const float* __restrict__ rvar,
       float* __restrict__ preout)
{
    const int BM = 128, BN = 64, BK = 16;
    __shared__ float As[BK][BM];
    __shared__ float Ws[BK][BN];
    int tid = threadIdx.x;
    int gm = blockIdx.x * BM;
    int wn = blockIdx.y * BN;
    int ty = tid >> 3;   // 0..15 -> 8 rows each
    int tx = tid & 7;    // 0..7  -> 8 cols each

    float acc[8][8];
    #pragma unroll
    for (int i = 0; i < 8; i++)
        #pragma unroll
        for (int j = 0; j < 8; j++) acc[i][j] = 0.f;

    const int npair = DUAL ? 2 : 1;
    for (int pair = 0; pair < npair; ++pair) {
        const float* A = (pair == 1) ? A2 : A1;
        const float* W = (pair == 1) ? W2 : W1;
        for (int kt = 0; kt < K; kt += BK) {
            // A tile: thread t loads row gm+t, 16 consecutive k (4x float4)
            {
                int row = gm + tid;
                if (row < M) {
                    const float4* p = (const float4*)(A + (size_t)row * K + kt);
                    #pragma unroll
                    for (int q = 0; q < 4; q++) {
                        float4 v = p[q];
                        As[q * 4 + 0][tid] = v.x;
                        As[q * 4 + 1][tid] = v.y;
                        As[q * 4 + 2][tid] = v.z;
                        As[q * 4 + 3][tid] = v.w;
                    }
                } else {
                    #pragma unroll
                    for (int k = 0; k < 16; k++) As[k][tid] = 0.f;
                }
            }
            // W tile: 16 x 64, 2 float4 per thread (N is always a multiple of 4)
            {
                #pragma unroll
                for (int q = 0; q < 2; q++) {
                    int s = tid * 2 + q;       // 0..255
                    int r = s >> 4;            // k row 0..15
                    int c4 = s & 15;           // float4 col 0..15
                    int gc = wn + c4 * 4;
                    float4 v = make_float4(0.f, 0.f, 0.f, 0.f);
                    if (gc < N) v = *(const float4*)(W + (size_t)(kt + r) * N + gc);
                    Ws[r][c4 * 4 + 0] = v.x;
                    Ws[r][c4 * 4 + 1] = v.y;
                    Ws[r][c4 * 4 + 2] = v.z;
                    Ws[r][c4 * 4 + 3] = v.w;
                }
            }
            __syncthreads();
            #pragma unroll
            for (int k = 0; k < BK; k++) {
                float a[8], w[8];
                #pragma unroll
                for (int i = 0; i < 8; i++) a[i] = As[k][ty * 8 + i];
                #pragma unroll
                for (int j = 0; j < 8; j++) w[j] = Ws[k][tx * 8 + j];
                #pragma unroll
                for (int i = 0; i < 8; i++)
                    #pragma unroll
                    for (int j = 0; j < 8; j++)
                        acc[i][j] += a[i] * w[j];
            }
            __syncthreads();
        }
    }

    #pragma unroll
    for (int i = 0; i < 8; i++) {
        int row = gm + ty * 8 + i;
        if (row >= M) continue;
        #pragma unroll
        for (int j = 0; j < 8; j++) {
            int col = wn + tx * 8 + j;
            if (col >= N) continue;
            float v = acc[i][j] + bias[col];
            if (MODE == 1) v = fmaxf(v, 0.f);
            if (MODE == 2) {
                float s = gamma[col] * rsqrtf(rvar[col] + 1e-5f);
                float t = beta[col] - rmean[col] * s;
                float p = v * s + t;
                preout[(size_t)row * N + col] = p;
                v = tanhf(p);
            }
            out[(size_t)row * N + col] = v;
        }
    }
}

// ---------------- true_lab: pre_bn[64] . wtl[64] + btl ----------------
__global__ void truelab_k(const float* __restrict__ wtl, const float* __restrict__ btl,
                          float* __restrict__ out) {
    int warp = (blockIdx.x * blockDim.x + threadIdx.x) >> 5;
    int lane = threadIdx.x & 31;
    if (warp >= NN) return;
    const float* p = g_prebn + (size_t)warp * NBITS;
    float s = p[lane] * wtl[lane] + p[lane + 32] * wtl[lane + 32];
    #pragma unroll
    for (int o = 16; o > 0; o >>= 1) s += __shfl_down_sync(0xffffffffu, s, o);
    if (lane == 0) out[warp] = s + btl[0];
}

// ---------------- launch ----------------
extern "C" void kernel_launch(void* const* d_in, const int* in_sizes, int n_in,
                              void* d_out, int out_size)
{
    const float* features = (const float*)d_in[0];
    const int*   edges    = (const int*)d_in[1];
    const float* w1l = (const float*)d_in[2];
    const float* b1l = (const float*)d_in[3];
    const float* w1r = (const float*)d_in[4];
    const float* w2l = (const float*)d_in[5];
    const float* b2l = (const float*)d_in[6];
    const float* w2r = (const float*)d_in[7];
    const float* whd = (const float*)d_in[8];
    const float* bhd = (const float*)d_in[9];
    const float* wclas = (const float*)d_in[10];
    const float* bclas = (const float*)d_in[11];
    const float* wconv = (const float*)d_in[12];
    const float* bconv = (const float*)d_in[13];
    const float* gamma = (const float*)d_in[14];
    const float* beta  = (const float*)d_in[15];
    const float* rm    = (const float*)d_in[16];
    const float* rv    = (const float*)d_in[17];
    const float* wtl   = (const float*)d_in[18];
    const float* btl   = (const float*)d_in[19];
    const float* wcv   = (const float*)d_in[20];
    const float* bcv   = (const float*)d_in[21];

    float* out = (float*)d_out;
    // output tuple flattened in order:
    float* o_logists = out;                                   // 50000*100
    float* o_out     = out + (size_t)NN * NCLS;               // 50000*64  @ 5,000,000
    float* o_fealab  = o_out + (size_t)NN * NBITS;            // 50000*300 @ 8,200,000
    float* o_feacv   = o_fealab + (size_t)NN * HDIM;          // 50000*100 @ 23,200,000
    float* o_truelab = o_feacv + (size_t)NN * NCLS;           // 50000     @ 28,200,000

    const int* esrc = edges;
    const int* edst = edges + NE;

    float *p_mean, *p_h1, *p_h2, *p_pre;
    cudaGetSymbolAddress((void**)&p_mean, g_mean);
    cudaGetSymbolAddress((void**)&p_h1, g_h1);
    cudaGetSymbolAddress((void**)&p_h2, g_h2);
    cudaGetSymbolAddress((void**)&p_pre, g_prebn);

    const int NB_SCAN = (NN + 511) / 512;  // 98

    // CSR build
    zero_k<<<(NN + 255) / 256, 256>>>();
    hist_k<<<512, 256>>>(edst);
    scan1_k<<<NB_SCAN, 512>>>();
    scan2_k<<<1, 32>>>(NB_SCAN);
    scan3_k<<<NB_SCAN, 512>>>();
    scatter_k<<<512, 256>>>(esrc, edst);

    const int AGG_BLOCKS = (NN * 32 + 255) / 256;
    dim3 gsage((NN + 127) / 128, FD / 64);     // 391 x 2

    // layer 1
    agg_k<<<AGG_BLOCKS, 256>>>(features, p_mean);
    gemm_k<1, true><<<gsage, 128>>>(p_mean, w1l, features, w1r, b1l, p_h1,
                                    NN, FD, FD, nullptr, nullptr, nullptr, nullptr, nullptr);
    // layer 2
    agg_k<<<AGG_BLOCKS, 256>>>(p_h1, p_mean);
    gemm_k<1, true><<<gsage, 128>>>(p_mean, w2l, p_h1, w2r, b2l, p_h2,
                                    NN, FD, FD, nullptr, nullptr, nullptr, nullptr, nullptr);

    // heads
    gemm_k<0, false><<<dim3((NN + 127) / 128, (HDIM + 63) / 64), 128>>>(
        p_h2, whd, nullptr, nullptr, bhd, o_fealab, NN, HDIM, FD,
        nullptr, nullptr, nullptr, nullptr, nullptr);
    gemm_k<0, false><<<dim3((NN + 127) / 128, (NCLS + 63) / 64), 128>>>(
        p_h2, wclas, nullptr, nullptr, bclas, o_logists, NN, NCLS, FD,
        nullptr, nullptr, nullptr, nullptr, nullptr);
    gemm_k<2, false><<<dim3((NN + 127) / 128, 1), 128>>>(
        p_h2, wconv, nullptr, nullptr, bconv, o_out, NN, NBITS, FD,
        gamma, beta, rm, rv, p_pre);
    gemm_k<0, false><<<dim3((NN + 127) / 128, (NCLS + 63) / 64), 128>>>(
        o_out, wcv, nullptr, nullptr, bcv, o_feacv, NN, NCLS, NBITS,
        nullptr, nullptr, nullptr, nullptr, nullptr);
    truelab_k<<<(NN * 32 + 255) / 256, 256>>>(wtl, btl, o_truelab);
}

// round 4
// speedup vs baseline: 2.1334x; 2.1334x over previous
#include <cuda_runtime.h>
#include <cuda_bf16.h>
#include <cstdint>

#define NN 50000
#define NE 800000
#define FD 128
#define NBITS 64
#define NCLS 100
#define HDIM 300

// ---------------- scratch (device globals: allocation-free) ----------------
__device__ int   g_cursor[NN];
__device__ int   g_rowptr[NN + 1];
__device__ int   g_partials[128];
__device__ int   g_col[NE];
__device__ float g_mean[NN * FD];
__device__ float g_h1[NN * FD];
__device__ float g_h2[NN * FD];
__device__ float g_prebn[NN * NBITS];

// ---------------- helpers ----------------
__device__ __forceinline__ uint32_t smem_u32(const void* p) {
    uint32_t a;
    asm("{ .reg .u64 t; cvta.to.shared.u64 t, %1; cvt.u32.u64 %0, t; }" : "=r"(a) : "l"(p));
    return a;
}

__device__ __forceinline__ void ldsm4(uint32_t& r0, uint32_t& r1, uint32_t& r2, uint32_t& r3,
                                      uint32_t addr) {
    asm volatile("ldmatrix.sync.aligned.m8n8.x4.shared.b16 {%0,%1,%2,%3}, [%4];"
                 : "=r"(r0), "=r"(r1), "=r"(r2), "=r"(r3) : "r"(addr));
}

__device__ __forceinline__ void mma16816(float* c, uint32_t a0, uint32_t a1, uint32_t a2,
                                         uint32_t a3, uint32_t b0, uint32_t b1) {
    asm volatile("mma.sync.aligned.m16n8k16.row.col.f32.bf16.bf16.f32 "
                 "{%0,%1,%2,%3},{%4,%5,%6,%7},{%8,%9},{%0,%1,%2,%3};"
                 : "+f"(c[0]), "+f"(c[1]), "+f"(c[2]), "+f"(c[3])
                 : "r"(a0), "r"(a1), "r"(a2), "r"(a3), "r"(b0), "r"(b1));
}

// swizzled byte OFFSET within a bf16 tile (row stride RB bytes)
template <int RB>
__device__ __forceinline__ int swoff(int row, int k) {
    return row * RB + (((k >> 3) ^ (row & 7)) << 4) + ((k & 7) << 1);
}

__device__ __forceinline__ uint32_t pack_hi(float x, float y) {
    __nv_bfloat162 t = __floats2bfloat162_rn(x, y);
    return *(uint32_t*)&t;
}
__device__ __forceinline__ uint32_t pack_lo(float x, float y) {
    float hx = __bfloat162float(__float2bfloat16(x));
    float hy = __bfloat162float(__float2bfloat16(y));
    __nv_bfloat162 t = __floats2bfloat162_rn(x - hx, y - hy);
    return *(uint32_t*)&t;
}

// ---------------- CSR build: counting sort by dst ----------------
__global__ void zero_k() {
    int i = blockIdx.x * blockDim.x + threadIdx.x;
    if (i < NN) g_cursor[i] = 0;
}
__global__ void hist_k(const int* __restrict__ dst) {
    for (int e = blockIdx.x * blockDim.x + threadIdx.x; e < NE; e += gridDim.x * blockDim.x)
        atomicAdd(&g_cursor[dst[e]], 1);
}
__global__ void scan1_k() {
    int i = blockIdx.x * 512 + threadIdx.x;
    int v = (i < NN) ? g_cursor[i] : 0;
    int lane = threadIdx.x & 31, w = threadIdx.x >> 5;
    int x = v;
    #pragma unroll
    for (int o = 1; o < 32; o <<= 1) {
        int y = __shfl_up_sync(0xffffffffu, x, o);
        if (lane >= o) x += y;
    }
    __shared__ int wsum[16];
    if (lane == 31) wsum[w] = x;
    __syncthreads();
    if (w == 0) {
        int s = (lane < 16) ? wsum[lane] : 0;
        #pragma unroll
        for (int o = 1; o < 16; o <<= 1) {
            int y = __shfl_up_sync(0xffffffffu, s, o);
            if (lane >= o) s += y;
        }
        if (lane < 16) wsum[lane] = s;
    }
    __syncthreads();
    int incl = x + (w > 0 ? wsum[w - 1] : 0);
    if (i < NN) g_rowptr[i] = incl - v;
    if (threadIdx.x == 511) g_partials[blockIdx.x] = incl;
}
__global__ void scan2_k(int nb) {
    int t = threadIdx.x;
    int v = (t < nb) ? g_partials[t] : 0;
    int lane = t & 31, w = t >> 5;
    int x = v;
    #pragma unroll
    for (int o = 1; o < 32; o <<= 1) {
        int y = __shfl_up_sync(0xffffffffu, x, o);
        if (lane >= o) x += y;
    }
    __shared__ int ws[4];
    if (lane == 31) ws[w] = x;
    __syncthreads();
    int add = 0;
    for (int b = 0; b < w; b++) add += ws[b];
    if (t < nb) g_partials[t] = x + add - v;
}
__global__ void scan3_k() {
    int i = blockIdx.x * 512 + threadIdx.x;
    if (i < NN) {
        int v = g_rowptr[i] + g_partials[blockIdx.x];
        g_rowptr[i] = v;
        g_cursor[i] = v;
    }
    if (i == 0) g_rowptr[NN] = NE;
}
__global__ void scatter_k(const int* __restrict__ src, const int* __restrict__ dst) {
    for (int e = blockIdx.x * blockDim.x + threadIdx.x; e < NE; e += gridDim.x * blockDim.x) {
        int pos = atomicAdd(&g_cursor[dst[e]], 1);
        g_col[pos] = src[e];
    }
}

// ---------------- mean aggregation: one warp per node ----------------
__global__ void agg_k(const float* __restrict__ x, float* __restrict__ out) {
    int warp = blockIdx.x * (blockDim.x >> 5) + (threadIdx.x >> 5);
    int lane = threadIdx.x & 31;
    if (warp >= NN) return;
    int beg = g_rowptr[warp], end = g_rowptr[warp + 1];
    float4 acc = make_float4(0.f, 0.f, 0.f, 0.f);
    for (int e = beg; e < end; ++e) {
        int s = __ldg(&g_col[e]);
        float4 v = *(const float4*)(x + (size_t)s * FD + lane * 4);
        acc.x += v.x; acc.y += v.y; acc.z += v.z; acc.w += v.w;
    }
    float sc = 1.f / (float)max(end - beg, 1);
    *(float4*)(out + (size_t)warp * FD + lane * 4) =
        make_float4(acc.x * sc, acc.y * sc, acc.z * sc, acc.w * sc);
}

// ---------------- mma.sync bf16-split GEMM ----------------
// C[M,N] = epi( A1@W1 (+A2@W2) + bias ), fp32 in/out.
// 3-term bf16 split: AhiBhi + AhiBlo + AloBhi (fp32 accum).
// BM=128, BN=64, 256 threads (8 warps, 4x2), warp tile 32x32.
// MODE 0: none, 1: relu, 2: BN(eval)+tanh (pre-BN -> preout, tanh -> out)
template <int MODE, bool DUAL, int K>
__global__ void __launch_bounds__(256)
mm_kernel(const float* __restrict__ A1, const float* __restrict__ W1,
          const float* __restrict__ A2, const float* __restrict__ W2,
          const float* __restrict__ bias, float* __restrict__ out,
          int M, int N,
          const float* __restrict__ gamma, const float* __restrict__ beta,
          const float* __restrict__ rmean, const float* __restrict__ rvar,
          float* __restrict__ preout)
{
    constexpr int RB  = K * 2;        // bytes per tile row
    constexpr int ATB = 128 * RB;
    constexpr int BTB = 64 * RB;
    extern __shared__ __align__(16) char smem[];
    // generic-space pointers for staging stores (STS via compiler)
    char* pAhi = smem;
    char* pAlo = smem + ATB;
    char* pBhi = smem + 2 * ATB;
    char* pBlo = smem + 2 * ATB + BTB;
    // shared-window u32 base addresses for ldmatrix only
    uint32_t sbase = smem_u32(smem);
    uint32_t sAhi = sbase, sAlo = sbase + ATB, sBhi = sbase + 2 * ATB, sBlo = sbase + 2 * ATB + BTB;

    int tid = threadIdx.x, lane = tid & 31, wid = tid >> 5;
    int wm  = (wid & 3) * 32;         // warp row offset in block
    int wnw = (wid >> 2) * 32;        // warp col offset in block
    int gm  = blockIdx.x * 128;
    int wn  = blockIdx.y * 64;

    float c[2][4][4];
    #pragma unroll
    for (int i = 0; i < 2; i++)
        #pragma unroll
        for (int j = 0; j < 4; j++)
            #pragma unroll
            for (int q = 0; q < 4; q++) c[i][j][q] = 0.f;

    // per-lane ldmatrix source coordinates
    int a_row = (lane & 15);                       // + m-tile base
    int a_kof = (lane >> 1) & 8;                   // +8 k for lanes 16..31
    int b_row = (lane & 7) + ((lane >> 1) & 8);    // n within 16-group
    int b_kof = lane & 8;

    const int npair = DUAL ? 2 : 1;
    for (int pair = 0; pair < npair; ++pair) {
        const float* A = pair ? A2 : A1;
        const float* W = pair ? W2 : W1;

        // stage A tile [128 x K] as hi/lo bf16, swizzled
        #pragma unroll 4
        for (int idx = tid; idx < 128 * (K / 4); idx += 256) {
            int row = idx / (K / 4);
            int q   = idx % (K / 4);
            int grow = gm + row;
            float4 v = make_float4(0.f, 0.f, 0.f, 0.f);
            if (grow < M) v = *(const float4*)(A + (size_t)grow * K + q * 4);
            int o0 = swoff<RB>(row, 4 * q);
            int o1 = swoff<RB>(row, 4 * q + 2);
            *(uint32_t*)(pAhi + o0) = pack_hi(v.x, v.y);
            *(uint32_t*)(pAhi + o1) = pack_hi(v.z, v.w);
            *(uint32_t*)(pAlo + o0) = pack_lo(v.x, v.y);
            *(uint32_t*)(pAlo + o1) = pack_lo(v.z, v.w);
        }
        // stage W tile transposed: smem row n (0..63), cols k — W gmem is [K x N]
        #pragma unroll 4
        for (int idx = tid; idx < (K / 2) * 64; idx += 256) {
            int n  = idx & 63;
            int kk = (idx >> 6) << 1;
            int gc = wn + n;
            float v0 = 0.f, v1 = 0.f;
            if (gc < N) {
                v0 = W[(size_t)kk * N + gc];
                v1 = W[(size_t)(kk + 1) * N + gc];
            }
            int o = swoff<RB>(n, kk);
            *(uint32_t*)(pBhi + o) = pack_hi(v0, v1);
            *(uint32_t*)(pBlo + o) = pack_lo(v0, v1);
        }
        __syncthreads();

        #pragma unroll
        for (int k0 = 0; k0 < K; k0 += 16) {
            uint32_t ah[2][4], al[2][4], bh[4][2], bl[4][2];
            #pragma unroll
            for (int mt = 0; mt < 2; mt++) {
                int oh = swoff<RB>(wm + mt * 16 + a_row, k0 + a_kof);
                ldsm4(ah[mt][0], ah[mt][1], ah[mt][2], ah[mt][3], sAhi + oh);
                ldsm4(al[mt][0], al[mt][1], al[mt][2], al[mt][3], sAlo + oh);
            }
            #pragma unroll
            for (int g = 0; g < 2; g++) {  // n 16-groups
                int ob = swoff<RB>(wnw + g * 16 + b_row, k0 + b_kof);
                ldsm4(bh[g * 2][0], bh[g * 2][1], bh[g * 2 + 1][0], bh[g * 2 + 1][1], sBhi + ob);
                ldsm4(bl[g * 2][0], bl[g * 2][1], bl[g * 2 + 1][0], bl[g * 2 + 1][1], sBlo + ob);
            }
            #pragma unroll
            for (int mt = 0; mt < 2; mt++)
                #pragma unroll
                for (int nt = 0; nt < 4; nt++) {
                    mma16816(c[mt][nt], ah[mt][0], ah[mt][1], ah[mt][2], ah[mt][3],
                             bh[nt][0], bh[nt][1]);
                    mma16816(c[mt][nt], ah[mt][0], ah[mt][1], ah[mt][2], ah[mt][3],
                             bl[nt][0], bl[nt][1]);
                    mma16816(c[mt][nt], al[mt][0], al[mt][1], al[mt][2], al[mt][3],
                             bh[nt][0], bh[nt][1]);
                }
        }
        __syncthreads();
    }

    // epilogue: fragment (mt, nt), thread element mapping
    int g  = lane >> 2;
    int tc = (lane & 3) * 2;
    #pragma unroll
    for (int mt = 0; mt < 2; mt++) {
        #pragma unroll
        for (int nt = 0; nt < 4; nt++) {
            int col0 = wn + wnw + nt * 8 + tc;
            #pragma unroll
            for (int h = 0; h < 2; h++) {          // h: row half (c0,c1) vs (c2,c3)
                int row = gm + wm + mt * 16 + g + h * 8;
                if (row >= M) continue;
                #pragma unroll
                for (int e = 0; e < 2; e++) {
                    int col = col0 + e;
                    if (col >= N) continue;
                    float v = c[mt][nt][h * 2 + e] + bias[col];
                    if (MODE == 1) v = fmaxf(v, 0.f);
                    if (MODE == 2) {
                        float s = gamma[col] * rsqrtf(rvar[col] + 1e-5f);
                        float t = beta[col] - rmean[col] * s;
                        float p = v * s + t;
                        preout[(size_t)row * N + col] = p;
                        v = tanhf(p);
                    }
                    out[(size_t)row * N + col] = v;
                }
            }
        }
    }
}

// ---------------- true_lab: pre_bn[64] . wtl[64] + btl ----------------
__global__ void truelab_k(const float* __restrict__ wtl, const float* __restrict__ btl,
                          float* __restrict__ out) {
    int warp = (blockIdx.x * blockDim.x + threadIdx.x) >> 5;
    int lane = threadIdx.x & 31;
    if (warp >= NN) return;
    const float* p = g_prebn + (size_t)warp * NBITS;
    float s = p[lane] * wtl[lane] + p[lane + 32] * wtl[lane + 32];
    #pragma unroll
    for (int o = 16; o > 0; o >>= 1) s += __shfl_down_sync(0xffffffffu, s, o);
    if (lane == 0) out[warp] = s + btl[0];
}

// ---------------- launch ----------------
extern "C" void kernel_launch(void* const* d_in, const int* in_sizes, int n_in,
                              void* d_out, int out_size)
{
    const float* features = (const float*)d_in[0];
    const int*   edges    = (const int*)d_in[1];
    const float* w1l = (const float*)d_in[2];
    const float* b1l = (const float*)d_in[3];
    const float* w1r = (const float*)d_in[4];
    const float* w2l = (const float*)d_in[5];
    const float* b2l = (const float*)d_in[6];
    const float* w2r = (const float*)d_in[7];
    const float* whd = (const float*)d_in[8];
    const float* bhd = (const float*)d_in[9];
    const float* wclas = (const float*)d_in[10];
    const float* bclas = (const float*)d_in[11];
    const float* wconv = (const float*)d_in[12];
    const float* bconv = (const float*)d_in[13];
    const float* gamma = (const float*)d_in[14];
    const float* beta  = (const float*)d_in[15];
    const float* rm    = (const float*)d_in[16];
    const float* rv    = (const float*)d_in[17];
    const float* wtl   = (const float*)d_in[18];
    const float* btl   = (const float*)d_in[19];
    const float* wcv   = (const float*)d_in[20];
    const float* bcv   = (const float*)d_in[21];

    float* out = (float*)d_out;
    float* o_logists = out;
    float* o_out     = out + (size_t)NN * NCLS;
    float* o_fealab  = o_out + (size_t)NN * NBITS;
    float* o_feacv   = o_fealab + (size_t)NN * HDIM;
    float* o_truelab = o_feacv + (size_t)NN * NCLS;

    const int* esrc = edges;
    const int* edst = edges + NE;

    float *p_mean, *p_h1, *p_h2, *p_pre;
    cudaGetSymbolAddress((void**)&p_mean, g_mean);
    cudaGetSymbolAddress((void**)&p_h1, g_h1);
    cudaGetSymbolAddress((void**)&p_h2, g_h2);
    cudaGetSymbolAddress((void**)&p_pre, g_prebn);

    const int SM128 = (2 * 128 + 2 * 64) * 128 * 2;  // 98304
    const int SM64  = (2 * 128 + 2 * 64) * 64 * 2;   // 49152
    cudaFuncSetAttribute(mm_kernel<1, true, 128>,  cudaFuncAttributeMaxDynamicSharedMemorySize, SM128);
    cudaFuncSetAttribute(mm_kernel<0, false, 128>, cudaFuncAttributeMaxDynamicSharedMemorySize, SM128);
    cudaFuncSetAttribute(mm_kernel<2, false, 128>, cudaFuncAttributeMaxDynamicSharedMemorySize, SM128);
    cudaFuncSetAttribute(mm_kernel<0, false, 64>,  cudaFuncAttributeMaxDynamicSharedMemorySize, SM64);

    const int NB_SCAN = (NN + 511) / 512;  // 98

    zero_k<<<(NN + 255) / 256, 256>>>();
    hist_k<<<512, 256>>>(edst);
    scan1_k<<<NB_SCAN, 512>>>();
    scan2_k<<<1, 128>>>(NB_SCAN);
    scan3_k<<<NB_SCAN, 512>>>();
    scatter_k<<<512, 256>>>(esrc, edst);

    const int AGG_BLOCKS = (NN * 32 + 255) / 256;
    const int GM = (NN + 127) / 128;  // 391

    // layer 1
    agg_k<<<AGG_BLOCKS, 256>>>(features, p_mean);
    mm_kernel<1, true, 128><<<dim3(GM, 2), 256, SM128>>>(
        p_mean, w1l, features, w1r, b1l, p_h1, NN, FD,
        nullptr, nullptr, nullptr, nullptr, nullptr);
    // layer 2
    agg_k<<<AGG_BLOCKS, 256>>>(p_h1, p_mean);
    mm_kernel<1, true, 128><<<dim3(GM, 2), 256, SM128>>>(
        p_mean, w2l, p_h1, w2r, b2l, p_h2, NN, FD,
        nullptr, nullptr, nullptr, nullptr, nullptr);

    // heads
    mm_kernel<0, false, 128><<<dim3(GM, (HDIM + 63) / 64), 256, SM128>>>(
        p_h2, whd, nullptr, nullptr, bhd, o_fealab, NN, HDIM,
        nullptr, nullptr, nullptr, nullptr, nullptr);
    mm_kernel<0, false, 128><<<dim3(GM, (NCLS + 63) / 64), 256, SM128>>>(
        p_h2, wclas, nullptr, nullptr, bclas, o_logists, NN, NCLS,
        nullptr, nullptr, nullptr, nullptr, nullptr);
    mm_kernel<2, false, 128><<<dim3(GM, 1), 256, SM128>>>(
        p_h2, wconv, nullptr, nullptr, bconv, o_out, NN, NBITS,
        gamma, beta, rm, rv, p_pre);
    mm_kernel<0, false, 64><<<dim3(GM, (NCLS + 63) / 64), 256, SM64>>>(
        o_out, wcv, nullptr, nullptr, bcv, o_feacv, NN, NCLS,
        nullptr, nullptr, nullptr, nullptr, nullptr);
    truelab_k<<<(NN * 32 + 255) / 256, 256>>>(wtl, btl, o_truelab);
}